// round 3
// baseline (speedup 1.0000x reference)
#include <cuda_runtime.h>

// TripletLoss2: B=4096 rows, D=4096 fp32 features.
// loss_i = hinge( s_near - s_far + 0.5*((l_i-l_far)^2 - (l_i-l_near)^2) )
// out = sum_i loss_i
//
// Single fused kernel: warp-per-row (8 rows per 256-thread CTA, grid=512).
// Each warp streams 3 rows (i, idx1, idx2) as float4, warp-shuffle reduces the
// two squared-L2 distances, computes the hinge, writes g_partials[row].
// The last CTA to retire (threadfence-reduction pattern) sums all 4096
// partials in a FIXED order (deterministic) and writes out[0], then resets
// the retirement counter so the kernel is CUDA-graph replayable.

#define NROWS 4096
#define NDIM  4096
#define MARGIN 0.5f
#define ROWS_PER_CTA 8
#define NCTAS (NROWS / ROWS_PER_CTA)   // 512

__device__ float        g_partials[NROWS];
__device__ unsigned int g_retired = 0;

__device__ __forceinline__ void acc_sq(const float4& a, const float4& b, float& s) {
    float d;
    d = a.x - b.x; s = fmaf(d, d, s);
    d = a.y - b.y; s = fmaf(d, d, s);
    d = a.z - b.z; s = fmaf(d, d, s);
    d = a.w - b.w; s = fmaf(d, d, s);
}

__global__ __launch_bounds__(256, 6)
void triplet_fused_kernel(const float* __restrict__ f,
                          const float* __restrict__ label,
                          const int*   __restrict__ idx1,
                          const int*   __restrict__ idx2,
                          float* __restrict__ out) {
    const int lane = threadIdx.x & 31;
    const int wid  = threadIdx.x >> 5;           // 0..7
    const int row  = blockIdx.x * ROWS_PER_CTA + wid;

    const int j1 = idx1[row];
    const int j2 = idx2[row];

    const float4* __restrict__ fi = (const float4*)(f + (size_t)row * NDIM);
    const float4* __restrict__ f1 = (const float4*)(f + (size_t)j1  * NDIM);
    const float4* __restrict__ f2 = (const float4*)(f + (size_t)j2  * NDIM);

    float s1 = 0.0f;   // ||f_i - f_idx1||^2 partial
    float s2 = 0.0f;   // ||f_i - f_idx2||^2 partial

    // 1024 float4 per row / 32 lanes = 32 steps; unroll x2 with front-batched
    // loads: 6 independent LDG.128 per lane between scoreboard waits.
    #pragma unroll
    for (int w = 0; w < 16; w++) {
        const int k0 = lane + (2 * w + 0) * 32;
        const int k1 = lane + (2 * w + 1) * 32;
        float4 a0 = fi[k0], b0 = f1[k0], c0 = f2[k0];
        float4 a1 = fi[k1], b1 = f1[k1], c1 = f2[k1];
        acc_sq(a0, b0, s1);
        acc_sq(a0, c0, s2);
        acc_sq(a1, b1, s1);
        acc_sq(a1, c1, s2);
    }

    // warp-local reduce (5 shuffle steps)
    #pragma unroll
    for (int off = 16; off > 0; off >>= 1) {
        s1 += __shfl_xor_sync(0xFFFFFFFFu, s1, off);
        s2 += __shfl_xor_sync(0xFFFFFFFFu, s2, off);
    }

    if (lane == 0) {
        const float li = label[row];
        const float l1 = label[j1];
        const float l2 = label[j2];
        const float d1 = fabsf(li - l1);
        const float d2 = fabsf(li - l2);
        const bool cond = (d1 >= d2);            // true -> idx2 is the near sample
        const float a2n   = cond ? s2 : s1;
        const float a2f   = cond ? s1 : s2;
        const float nearl = cond ? l2 : l1;
        const float farl  = cond ? l1 : l2;
        const float dn = li - nearl;
        const float df = li - farl;
        const float alpha = df * df - dn * dn;
        const float loss = a2n - a2f + alpha * MARGIN;
        g_partials[row] = fmaxf(loss, 0.0f);
    }

    // ---- fused final reduction: last CTA to retire sums all partials ----
    __shared__ bool s_is_last;
    __syncthreads();                // all 8 warps' partials written
    if (threadIdx.x == 0) {
        __threadfence();            // make this CTA's partials globally visible
        unsigned int prev = atomicAdd(&g_retired, 1u);
        s_is_last = (prev == NCTAS - 1);
    }
    __syncthreads();

    if (s_is_last) {
        __threadfence();            // see all other CTAs' partials
        // fixed-order accumulation -> deterministic result
        float acc = 0.0f;
        #pragma unroll
        for (int k = 0; k < NROWS / 256; k++)   // 16 strided reads per thread
            acc += g_partials[threadIdx.x + k * 256];

        #pragma unroll
        for (int off = 16; off > 0; off >>= 1)
            acc += __shfl_xor_sync(0xFFFFFFFFu, acc, off);

        __shared__ float sh[8];
        if (lane == 0) sh[wid] = acc;
        __syncthreads();
        if (wid == 0) {
            float t = (lane < 8) ? sh[lane] : 0.0f;
            #pragma unroll
            for (int off = 4; off > 0; off >>= 1)
                t += __shfl_xor_sync(0xFFFFFFFFu, t, off);
            if (lane == 0) {
                out[0] = t;
                g_retired = 0;      // reset for next graph replay
            }
        }
    }
}

extern "C" void kernel_launch(void* const* d_in, const int* in_sizes, int n_in,
                              void* d_out, int out_size) {
    const float* f     = (const float*)d_in[0];
    const float* label = (const float*)d_in[1];
    const int*   idx1  = (const int*)d_in[2];
    const int*   idx2  = (const int*)d_in[3];
    float* out = (float*)d_out;

    triplet_fused_kernel<<<NCTAS, 256>>>(f, label, idx1, idx2, out);
}

// round 4
// speedup vs baseline: 1.0821x; 1.0821x over previous
#include <cuda_runtime.h>

// TripletLoss2: B=4096 rows, D=4096 fp32 features.
// loss_i = hinge( s_near - s_far + 0.5*((l_i-l_far)^2 - (l_i-l_near)^2) )
// out = sum_i loss_i
//
// R4: latency-bound fix — 2 warps per row (D split in half) doubles total
// warps 4096 -> 8192 (occ 43% -> ~86%), doubling in-flight LDG.128s.
// 256-thread CTA = 8 warps = 4 rows; grid = 1024.
// Halves combine via smem; last CTA does deterministic fixed-order final sum.

#define NROWS 4096
#define NDIM  4096
#define MARGIN 0.5f
#define ROWS_PER_CTA 4
#define NCTAS (NROWS / ROWS_PER_CTA)   // 1024

__device__ float        g_partials[NROWS];
__device__ unsigned int g_retired = 0;

__device__ __forceinline__ void acc_sq(const float4& a, const float4& b, float& s) {
    float d;
    d = a.x - b.x; s = fmaf(d, d, s);
    d = a.y - b.y; s = fmaf(d, d, s);
    d = a.z - b.z; s = fmaf(d, d, s);
    d = a.w - b.w; s = fmaf(d, d, s);
}

__global__ __launch_bounds__(256, 8)
void triplet_fused_kernel(const float* __restrict__ f,
                          const float* __restrict__ label,
                          const int*   __restrict__ idx1,
                          const int*   __restrict__ idx2,
                          float* __restrict__ out) {
    const int lane  = threadIdx.x & 31;
    const int wid   = threadIdx.x >> 5;          // 0..7
    const int rloc  = wid >> 1;                  // 0..3 row within CTA
    const int half  = wid & 1;                   // 0 or 1: which D-half
    const int row   = blockIdx.x * ROWS_PER_CTA + rloc;

    const int j1 = idx1[row];
    const int j2 = idx2[row];

    // Half-row base: 512 float4 per half
    const size_t hoff = (size_t)half * (NDIM / 8);   // in float4 units: 512
    const float4* __restrict__ fi = (const float4*)(f + (size_t)row * NDIM) + hoff;
    const float4* __restrict__ f1 = (const float4*)(f + (size_t)j1  * NDIM) + hoff;
    const float4* __restrict__ f2 = (const float4*)(f + (size_t)j2  * NDIM) + hoff;

    float s1 = 0.0f;   // ||.||^2 partial vs idx1 (this half)
    float s2 = 0.0f;   // vs idx2

    // 512 float4 / 32 lanes = 16 steps; unroll x2, front-batched loads:
    // 6 independent LDG.128 per lane between scoreboard waits.
    #pragma unroll
    for (int w = 0; w < 8; w++) {
        const int k0 = lane + (2 * w + 0) * 32;
        const int k1 = lane + (2 * w + 1) * 32;
        float4 a0 = fi[k0], b0 = f1[k0], c0 = f2[k0];
        float4 a1 = fi[k1], b1 = f1[k1], c1 = f2[k1];
        acc_sq(a0, b0, s1);
        acc_sq(a0, c0, s2);
        acc_sq(a1, b1, s1);
        acc_sq(a1, c1, s2);
    }

    // warp-local reduce (5 shuffle steps)
    #pragma unroll
    for (int off = 16; off > 0; off >>= 1) {
        s1 += __shfl_xor_sync(0xFFFFFFFFu, s1, off);
        s2 += __shfl_xor_sync(0xFFFFFFFFu, s2, off);
    }

    // combine the two half-row partials via smem
    __shared__ float sh_s1[8];
    __shared__ float sh_s2[8];
    if (lane == 0) { sh_s1[wid] = s1; sh_s2[wid] = s2; }
    __syncthreads();

    if (half == 0 && lane == 0) {
        const float t1 = sh_s1[wid] + sh_s1[wid + 1];   // fixed order: deterministic
        const float t2 = sh_s2[wid] + sh_s2[wid + 1];

        const float li = label[row];
        const float l1 = label[j1];
        const float l2 = label[j2];
        const float d1 = fabsf(li - l1);
        const float d2 = fabsf(li - l2);
        const bool cond = (d1 >= d2);            // true -> idx2 is the near sample
        const float a2n   = cond ? t2 : t1;
        const float a2f   = cond ? t1 : t2;
        const float nearl = cond ? l2 : l1;
        const float farl  = cond ? l1 : l2;
        const float dn = li - nearl;
        const float df = li - farl;
        const float alpha = df * df - dn * dn;
        const float loss = a2n - a2f + alpha * MARGIN;
        g_partials[row] = fmaxf(loss, 0.0f);
    }

    // ---- fused final reduction: last CTA to retire sums all partials ----
    __shared__ bool s_is_last;
    __syncthreads();                // all rows' partials of this CTA written
    if (threadIdx.x == 0) {
        __threadfence();            // make this CTA's partials globally visible
        unsigned int prev = atomicAdd(&g_retired, 1u);
        s_is_last = (prev == NCTAS - 1);
    }
    __syncthreads();

    if (s_is_last) {
        __threadfence();            // see all other CTAs' partials
        // fixed-order accumulation -> deterministic result
        float acc = 0.0f;
        #pragma unroll
        for (int k = 0; k < NROWS / 256; k++)   // 16 strided reads per thread
            acc += g_partials[threadIdx.x + k * 256];

        #pragma unroll
        for (int off = 16; off > 0; off >>= 1)
            acc += __shfl_xor_sync(0xFFFFFFFFu, acc, off);

        __shared__ float shf[8];
        if (lane == 0) shf[wid] = acc;
        __syncthreads();
        if (wid == 0) {
            float t = (lane < 8) ? shf[lane] : 0.0f;
            #pragma unroll
            for (int off = 4; off > 0; off >>= 1)
                t += __shfl_xor_sync(0xFFFFFFFFu, t, off);
            if (lane == 0) {
                out[0] = t;
                g_retired = 0;      // reset for next graph replay
            }
        }
    }
}

extern "C" void kernel_launch(void* const* d_in, const int* in_sizes, int n_in,
                              void* d_out, int out_size) {
    const float* f     = (const float*)d_in[0];
    const float* label = (const float*)d_in[1];
    const int*   idx1  = (const int*)d_in[2];
    const int*   idx2  = (const int*)d_in[3];
    float* out = (float*)d_out;

    triplet_fused_kernel<<<NCTAS, 256>>>(f, label, idx1, idx2, out);
}